// round 6
// baseline (speedup 1.0000x reference)
#include <cuda_runtime.h>
#include <cstddef>

// Problem constants
#define B_  8
#define T_  2048
#define D_  256
#define DK_ 64
#define NHEAD_ 4

// Fused attention kernel tiling
#define R_    16     // query rows per CTA
#define ST_   128    // key/value tile along s
#define TH_   1024   // threads per CTA
#define KPAD  68
#define KVBUF (ST_ * KPAD)   // 8704 floats per buffer

// Scratch for projected q/k/v  (8*2048*64 fp32 = 4 MB each)
__device__ float g_qs[B_ * T_ * DK_];
__device__ float g_ks[B_ * T_ * DK_];
__device__ float g_vs[B_ * T_ * DK_];

// ---- packed f32x2 helpers (SASS FFMA2 — PTX-only pattern) ------------------
__device__ __forceinline__ void ffma2(unsigned long long& acc,
                                      unsigned long long a,
                                      unsigned long long b) {
    asm("fma.rn.f32x2 %0, %1, %2, %0;" : "+l"(acc) : "l"(a), "l"(b));
}
__device__ __forceinline__ unsigned long long pack2(float lo, float hi) {
    unsigned long long r;
    asm("mov.b64 %0, {%1, %2};" : "=l"(r) : "f"(lo), "f"(hi));
    return r;
}
__device__ __forceinline__ float pairsum(unsigned long long p) {
    float lo, hi;
    asm("mov.b64 {%0, %1}, %2;" : "=f"(lo), "=f"(hi) : "l"(p));
    return lo + hi;
}
__device__ __forceinline__ void unpack2(float& lo, float& hi, unsigned long long p) {
    asm("mov.b64 {%0, %1}, %2;" : "=f"(lo), "=f"(hi) : "l"(p));
}

// ---------------------------------------------------------------------------
// Kernel 1: projections  qs = q@Wq, ks = k@Wk, vs = v@Wv
// grid = (512, 3), block = 256.  Block: 32 rows x 64 cols; smem 96KB -> 2 CTA/SM
// ---------------------------------------------------------------------------
#define PROJ_TH 256
#define PROJ_ROWS 32
#define PROJ_SMEM ((PROJ_ROWS * 256 + 256 * DK_) * 4)   // 32KB + 64KB

__global__ __launch_bounds__(PROJ_TH, 2)
void proj_kernel(const float* __restrict__ q,
                 const float* __restrict__ k,
                 const float* __restrict__ v,
                 const float* __restrict__ Wq,
                 const float* __restrict__ Wk,
                 const float* __restrict__ Wv) {
    extern __shared__ float psm[];
    float* xs = psm;                       // 32*256
    float* Ws = psm + PROJ_ROWS * 256;     // 256*64

    const float* x;
    const float* W;
    float* dst;
    if (blockIdx.y == 0)      { x = q; W = Wq; dst = g_qs; }
    else if (blockIdx.y == 1) { x = k; W = Wk; dst = g_ks; }
    else                      { x = v; W = Wv; dst = g_vs; }

    const int row0 = blockIdx.x * PROJ_ROWS;
    const int tid  = threadIdx.x;

    {
        const float4* src4 = reinterpret_cast<const float4*>(x + (size_t)row0 * D_);
        float4* xs4 = reinterpret_cast<float4*>(xs);
        #pragma unroll
        for (int i = tid; i < PROJ_ROWS * 256 / 4; i += PROJ_TH) xs4[i] = src4[i];
        const float4* w4 = reinterpret_cast<const float4*>(W);
        float4* ws4 = reinterpret_cast<float4*>(Ws);
        #pragma unroll
        for (int i = tid; i < 256 * DK_ / 4; i += PROJ_TH) ws4[i] = w4[i];
    }
    __syncthreads();

    // thread tile: 2 rows x 4 cols
    const int jg = tid & 15;
    const int rg = tid >> 4;          // 0..15
    const int j0 = jg * 4;
    const int r0 = rg * 2;

    unsigned long long acc2[2][2];
    acc2[0][0] = acc2[0][1] = acc2[1][0] = acc2[1][1] = 0ULL;

    for (int i = 0; i < D_; i += 4) {
        float4 xa = *reinterpret_cast<const float4*>(&xs[r0 * 256 + i]);
        float4 xb = *reinterpret_cast<const float4*>(&xs[(r0 + 1) * 256 + i]);
        #pragma unroll
        for (int ii = 0; ii < 4; ii++) {
            ulonglong2 w2 = *reinterpret_cast<const ulonglong2*>(&Ws[(i + ii) * DK_ + j0]);
            const float xav = (ii == 0) ? xa.x : (ii == 1) ? xa.y : (ii == 2) ? xa.z : xa.w;
            const float xbv = (ii == 0) ? xb.x : (ii == 1) ? xb.y : (ii == 2) ? xb.z : xb.w;
            const unsigned long long xa2 = pack2(xav, xav);
            const unsigned long long xb2 = pack2(xbv, xbv);
            ffma2(acc2[0][0], xa2, w2.x);
            ffma2(acc2[0][1], xa2, w2.y);
            ffma2(acc2[1][0], xb2, w2.x);
            ffma2(acc2[1][1], xb2, w2.y);
        }
    }

    #pragma unroll
    for (int r = 0; r < 2; r++) {
        float a0, a1, a2, a3;
        unpack2(a0, a1, acc2[r][0]);
        unpack2(a2, a3, acc2[r][1]);
        float4* o = reinterpret_cast<float4*>(&dst[(size_t)(row0 + r0 + r) * DK_ + j0]);
        *o = make_float4(a0, a1, a2, a3);
    }
}

// ---------------------------------------------------------------------------
// Kernel 2: fused  scores -> softmax -> write attn x4 -> attn@V -> @Wo
// grid = 1024 CTAs, block = 1024 threads (32 warps).
// smem: sc[16*2048] + kv[2][128*68] + qh[16*64] + rinv[16] + part[64] ~ 200KB
// ---------------------------------------------------------------------------
#define SMEM_FLOATS (R_ * T_ + 2 * KVBUF + R_ * DK_ + 16 + 64)
#define SMEM_BYTES  (SMEM_FLOATS * 4)

__global__ __launch_bounds__(TH_, 1)
void attn_kernel(const float* __restrict__ Wo,
                 float* __restrict__ out,
                 float* __restrict__ attn_out) {
    extern __shared__ float sm[];
    float* sc   = sm;                        // 32768 floats (128 KB)
    float* kv   = sc + R_ * T_;              // 2 * 8704 floats
    float* qh   = kv + 2 * KVBUF;            // 1024 floats
    float* rinv = qh + R_ * DK_;             // 16
    float* part = rinv + 16;                 // 64 (row partials)

    const int tid = threadIdx.x;
    const int b   = blockIdx.x >> 7;
    const int t0  = (blockIdx.x & 127) * R_;

    const float* ksrc = g_ks + (size_t)b * T_ * DK_;
    const float* vsrc = g_vs + (size_t)b * T_ * DK_;

    // ---- load q tile --------------------------------------------------------
    {
        const size_t qbase = ((size_t)b * T_ + t0) * DK_;
        for (int i = tid; i < R_ * DK_; i += TH_) qh[i] = g_qs[qbase + i];
    }

    // ---- phase 1: scores = qs . ks^T * 0.125 --------------------------------
    // thread: 4 rows x 1 s x 32 d; d-half partner = lane xor 8 (shfl reduce).
    {
        const int dh = (tid >> 3) & 1;                   // d half
        const int sg = (tid & 7) | ((tid >> 1) & 0x78);  // 0..127
        const int rg = tid >> 8;                         // 0..3
        const int d0 = dh * 32;

        // prefill tile 0
        {
            const float4* k4 = reinterpret_cast<const float4*>(ksrc);
            for (int i = tid; i < ST_ * 16; i += TH_) {
                const int s = i >> 4, dq = i & 15;
                *reinterpret_cast<float4*>(&kv[s * KPAD + dq * 4]) = k4[i];
            }
        }
        __syncthreads();

        for (int t = 0; t < T_ / ST_; t++) {
            const int st = t * ST_;
            float* cur = kv + (t & 1) * KVBUF;

            // prefetch next tile into other buffer
            if (st + ST_ < T_) {
                float* nxt = kv + ((t + 1) & 1) * KVBUF;
                const float4* k4 =
                    reinterpret_cast<const float4*>(ksrc + (size_t)(st + ST_) * DK_);
                for (int i = tid; i < ST_ * 16; i += TH_) {
                    const int s = i >> 4, dq = i & 15;
                    *reinterpret_cast<float4*>(&nxt[s * KPAD + dq * 4]) = k4[i];
                }
            }

            unsigned long long acc2[4] = {0ULL, 0ULL, 0ULL, 0ULL};
            #pragma unroll
            for (int dd = 0; dd < 32; dd += 4) {
                const int d = d0 + dd;
                ulonglong2 k2 = *reinterpret_cast<const ulonglong2*>(&cur[sg * KPAD + d]);
                #pragma unroll
                for (int r = 0; r < 4; r++) {
                    ulonglong2 q2 = *reinterpret_cast<const ulonglong2*>(
                        &qh[(rg * 4 + r) * DK_ + d]);
                    ffma2(acc2[r], q2.x, k2.x);
                    ffma2(acc2[r], q2.y, k2.y);
                }
            }
            #pragma unroll
            for (int r = 0; r < 4; r++) {
                float v = pairsum(acc2[r]);
                v += __shfl_xor_sync(0xffffffffu, v, 8);
                if ((r >> 1) == dh)
                    sc[(rg * 4 + r) * T_ + st + sg] = v * 0.125f;
            }
            __syncthreads();
        }
    }

    // ---- phase 2: softmax (2 warps per row) ---------------------------------
    {
        const int row  = tid >> 6;          // 16 rows
        const int half = (tid >> 5) & 1;
        const int lane = tid & 31;
        float* rp = sc + row * T_ + half * 1024;

        float m = -1e30f;
        for (int s = lane; s < 1024; s += 32) m = fmaxf(m, rp[s]);
        #pragma unroll
        for (int o = 16; o > 0; o >>= 1)
            m = fmaxf(m, __shfl_xor_sync(0xffffffffu, m, o));
        if (lane == 0) part[row * 2 + half] = m;
        __syncthreads();

        const float M = fmaxf(part[row * 2], part[row * 2 + 1]);
        float sum = 0.f;
        for (int s = lane; s < 1024; s += 32) {
            const float p = __expf(rp[s] - M);
            rp[s] = p;
            sum += p;
        }
        #pragma unroll
        for (int o = 16; o > 0; o >>= 1)
            sum += __shfl_xor_sync(0xffffffffu, sum, o);
        if (lane == 0) part[32 + row * 2 + half] = sum;
        __syncthreads();

        if (tid < 16) rinv[tid] = 1.0f / (part[32 + tid * 2] + part[32 + tid * 2 + 1]);
        __syncthreads();
    }

    // ---- phase 3: normalize in place + write attn to all 4 heads ------------
    {
        const size_t HTT   = (size_t)B_ * T_ * T_;
        const size_t abase = ((size_t)b * T_ + t0) * T_;
        float4* sc4 = reinterpret_cast<float4*>(sc);
        for (int i = tid; i < R_ * T_ / 4; i += TH_) {
            const int rr = i >> 9;
            const int s4 = i & 511;
            const float inv = rinv[rr];
            float4 vv = sc4[i];
            vv.x *= inv; vv.y *= inv; vv.z *= inv; vv.w *= inv;
            sc4[i] = vv;
            const size_t off = abase + (size_t)rr * T_ + (size_t)s4 * 4;
            #pragma unroll
            for (int h = 0; h < NHEAD_; h++)
                *reinterpret_cast<float4*>(attn_out + (size_t)h * HTT + off) = vv;
        }
    }
    __syncthreads();

    // ---- phase 4: head = attn @ vs  (tile 4r x 4d, 16-way s-split) ----------
    {
        const int dg  = tid & 15;           // 16 d groups (4 d each)
        const int rg4 = (tid >> 4) & 3;     // 4 row groups
        const int ss  = tid >> 6;           // 16 s subgroups (8 s each per tile)
        const int d4  = dg * 4;

        unsigned long long acc2[4][2];
        #pragma unroll
        for (int r = 0; r < 4; r++) { acc2[r][0] = 0ULL; acc2[r][1] = 0ULL; }

        // prefill v tile 0 (stride 64, no pad)
        {
            const float4* v4 = reinterpret_cast<const float4*>(vsrc);
            float4* dst4 = reinterpret_cast<float4*>(kv);
            for (int i = tid; i < ST_ * DK_ / 4; i += TH_) dst4[i] = v4[i];
        }
        __syncthreads();

        for (int t = 0; t < T_ / ST_; t++) {
            const int st = t * ST_;
            float* cur = kv + (t & 1) * KVBUF;

            if (st + ST_ < T_) {
                float* nxt = kv + ((t + 1) & 1) * KVBUF;
                const float4* v4 =
                    reinterpret_cast<const float4*>(vsrc + (size_t)(st + ST_) * DK_);
                float4* dst4 = reinterpret_cast<float4*>(nxt);
                for (int i = tid; i < ST_ * DK_ / 4; i += TH_) dst4[i] = v4[i];
            }

            const int sbase = ss * 8;
            #pragma unroll
            for (int j = 0; j < 8; j++) {
                const int sl = sbase + j;
                ulonglong2 v2 = *reinterpret_cast<const ulonglong2*>(&cur[sl * DK_ + d4]);
                #pragma unroll
                for (int r = 0; r < 4; r++) {
                    const float p = sc[(rg4 * 4 + r) * T_ + st + sl];
                    const unsigned long long p2 = pack2(p, p);
                    ffma2(acc2[r][0], p2, v2.x);
                    ffma2(acc2[r][1], p2, v2.y);
                }
            }
            __syncthreads();
        }

        // reduce the 16 s-subgroups via smem (reuse kv: 1024*17 = 17408 floats)
        #pragma unroll
        for (int r = 0; r < 4; r++) {
            float a0, a1, a2, a3;
            unpack2(a0, a1, acc2[r][0]);
            unpack2(a2, a3, acc2[r][1]);
            kv[tid * 17 + r * 4 + 0] = a0;
            kv[tid * 17 + r * 4 + 1] = a1;
            kv[tid * 17 + r * 4 + 2] = a2;
            kv[tid * 17 + r * 4 + 3] = a3;
        }
        __syncthreads();

        {
            const int pos = tid >> 4;       // (rg4<<4)|dg  : 64 positions
            const int i   = tid & 15;       // (r<<2)|c
            float s = 0.f;
            #pragma unroll
            for (int j = 0; j < 16; j++) s += kv[(pos + 64 * j) * 17 + i];
            const int prg = pos >> 4, pdg = pos & 15;
            const int r = i >> 2, c = i & 3;
            qh[(prg * 4 + r) * DK_ + pdg * 4 + c] = s;
        }
    }
    __syncthreads();

    // ---- phase 5: outputs = head @ Wo  (thread = column, 4 rows) ------------
    {
        const int c  = tid & 255;
        const int rh = tid >> 8;            // 4 row quarters
        float o[4] = {0.f, 0.f, 0.f, 0.f};

        for (int d = 0; d < DK_; d++) {
            const float w = Wo[(size_t)d * D_ + c];
            #pragma unroll
            for (int rr = 0; rr < 4; rr++)
                o[rr] += qh[(rh * 4 + rr) * DK_ + d] * w;
        }
        const size_t obase = ((size_t)b * T_ + t0 + rh * 4) * D_ + c;
        #pragma unroll
        for (int rr = 0; rr < 4; rr++) out[obase + (size_t)rr * D_] = o[rr];
    }
}

// ---------------------------------------------------------------------------
// launch
// ---------------------------------------------------------------------------
extern "C" void kernel_launch(void* const* d_in, const int* in_sizes, int n_in,
                              void* d_out, int out_size) {
    const float* q  = (const float*)d_in[0];
    const float* k  = (const float*)d_in[1];
    const float* v  = (const float*)d_in[2];
    const float* Wq = (const float*)d_in[3];
    const float* Wk = (const float*)d_in[4];
    const float* Wv = (const float*)d_in[5];
    const float* Wo = (const float*)d_in[6];

    float* out      = (float*)d_out;                               // [8,2048,256]
    float* attn_out = (float*)d_out + (size_t)B_ * T_ * D_;        // [4,8,2048,2048]

    cudaFuncSetAttribute(proj_kernel, cudaFuncAttributeMaxDynamicSharedMemorySize,
                         PROJ_SMEM);
    dim3 gp(16384 / PROJ_ROWS, 3, 1);
    proj_kernel<<<gp, PROJ_TH, PROJ_SMEM>>>(q, k, v, Wq, Wk, Wv);

    cudaFuncSetAttribute(attn_kernel, cudaFuncAttributeMaxDynamicSharedMemorySize,
                         SMEM_BYTES);
    attn_kernel<<<B_ * (T_ / R_), TH_, SMEM_BYTES>>>(Wo, out, attn_out);
}